// round 13
// baseline (speedup 1.0000x reference)
#include <cuda_runtime.h>
#include <math_constants.h>

// Problem constants (from reference setup_inputs)
#define N_IMG 2
#define C_CH  256
#define H_F   64
#define W_F   64
#define HW    (H_F * W_F)
#define R_ROI 128
#define PH    7
#define PW    7
#define NBINS (PH * PW)   // 49
#define SCALE 0.0625f
#define C4    (C_CH / 4)       // 64 float4 per pixel
#define ROWSTRIDE4 (W_F * C4)  // 4096 float4 per feature row
#define FULLMASK 0xffffffffu

// NHWC scratch: [b][h][w][c], 8 MB
__device__ float TFEAT[N_IMG * HW * C_CH];
// packed bounds per (r, bin): b<<28 | hs<<21 | he<<14 | ws<<7 | we
__device__ unsigned int BNDS[R_ROI * NBINS];

// ---------------------------------------------------------------------------
// Kernel 1: NCHW -> NHWC transpose (float4 both sides) + bounds precompute
// folded into the first 25 blocks. Bounds arithmetic VERBATIM bit-exact.
// ---------------------------------------------------------------------------
__global__ __launch_bounds__(256) void transpose_kernel(const float* __restrict__ feat,
                                                        const float* __restrict__ rois)
{
    __shared__ float tile[32][33];
    int b   = blockIdx.z;
    int hw0 = blockIdx.x * 32;
    int c0  = blockIdx.y * 32;
    int tx  = threadIdx.x;   // 0..7
    int ty  = threadIdx.y;   // 0..31
    int tid = ty * 8 + tx;

    if (blockIdx.y == 0 && blockIdx.z == 0 && blockIdx.x < 25) {
        int idx = blockIdx.x * 256 + tid;
        if (idx < R_ROI * NBINS) {
            int r   = idx / NBINS;
            int bin = idx - r * NBINS;
            int ph  = bin / PW;
            int pw  = bin - ph * PW;

            const float* roi = rois + r * 5;
            int bb = (int)roi[0];
            int sw = (int)rintf(roi[1] * SCALE);
            int sh_ = (int)rintf(roi[2] * SCALE);
            int ew = (int)rintf(roi[3] * SCALE);
            int eh = (int)rintf(roi[4] * SCALE);

            float roi_w = (float)max(ew - sw + 1, 1);
            float roi_h = (float)max(eh - sh_ + 1, 1);
            float bin_h = roi_h * (1.0f / PH);   // bit-exact vs reference
            float bin_w = roi_w * (1.0f / PW);

            int hs = min(max((int)floorf((float)ph * bin_h) + sh_, 0), H_F);
            int he = min(max((int)ceilf(((float)ph + 1.0f) * bin_h) + sh_, 0), H_F);
            int ws = min(max((int)floorf((float)pw * bin_w) + sw, 0), W_F);
            int we = min(max((int)ceilf(((float)pw + 1.0f) * bin_w) + sw, 0), W_F);

            BNDS[idx] = ((unsigned)bb << 28) | ((unsigned)hs << 21) |
                        ((unsigned)he << 14) | ((unsigned)ws << 7) | (unsigned)we;
        }
    }

    const float4* src4 = (const float4*)(feat + (size_t)b * C_CH * HW);
    float4*       dst4 = (float4*)(TFEAT + (size_t)b * HW * C_CH);

    float4 v = src4[(size_t)(c0 + ty) * (HW / 4) + (hw0 / 4) + tx];
    tile[ty][4 * tx + 0] = v.x;
    tile[ty][4 * tx + 1] = v.y;
    tile[ty][4 * tx + 2] = v.z;
    tile[ty][4 * tx + 3] = v.w;
    __syncthreads();

    float4 o;
    o.x = tile[4 * tx + 0][ty];
    o.y = tile[4 * tx + 1][ty];
    o.z = tile[4 * tx + 2][ty];
    o.w = tile[4 * tx + 3][ty];
    dst4[(size_t)(hw0 + ty) * C4 + (c0 / 4) + tx] = o;
}

// ---------------------------------------------------------------------------
// Kernel 2: row-scan pool.
// Block = (r, half, ph), 128 threads = 4 warps (warp = h-phase 0..3).
// Each warp scans rows h = hs+hp, hs+hp+4, ... of the ROI; for each row it
// walks each bin's exact [ws,we) range once (no duplicate reads), folding
// into 7 per-bin float4 accumulators (lane = 4 consecutive channels, one
// LDG.128 = one pixel x 128 channels). 4 h-phase warps combine via shared
// memory; -inf (never touched) maps to 0 = reference empty-bin semantics.
// ---------------------------------------------------------------------------
__global__ __launch_bounds__(128) void pool_kernel(float* __restrict__ out)
{
    __shared__ float sacc[4][7][128];  // [hp][pw][channel]
    __shared__ float tr[128][9];       // [channel][pw], pad 9 (conflict-free)

    int blk  = blockIdx.x;             // r*14 + half*7 + ph
    int ph   = blk % 7;
    int half = (blk / 7) & 1;
    int r    = blk / 14;
    int tid  = threadIdx.x;            // 0..127
    int hp   = tid >> 5;               // h-phase (warp id)
    int lane = tid & 31;

    // lane pw-word (lanes 0..6 hold the 7 bins of this ph row)
    unsigned bnd = __ldg(&BNDS[r * NBINS + ph * PW + min(lane, 6)]);
    int hs = (bnd >> 21) & 0x7f;       // identical across the row
    int he = (bnd >> 14) & 0x7f;
    int b  = bnd >> 28;

    // broadcast per-bin w-ranges into registers
    int wsv[7], wev[7];
    #pragma unroll
    for (int t = 0; t < 7; ++t) {
        unsigned bw = __shfl_sync(FULLMASK, bnd, t);
        wsv[t] = (bw >> 7) & 0x7f;
        wev[t] = bw & 0x7f;
    }

    float4 acc[7];
    #pragma unroll
    for (int t = 0; t < 7; ++t)
        acc[t] = make_float4(-CUDART_INF_F, -CUDART_INF_F, -CUDART_INF_F, -CUDART_INF_F);

    const float4* base = (const float4*)TFEAT + (b * HW * C4 + half * 32 + lane);
    for (int h = hs + hp; h < he; h += 4) {
        const float4* rowp = base + h * ROWSTRIDE4;
        #pragma unroll
        for (int t = 0; t < 7; ++t) {
            for (int w = wsv[t]; w < wev[t]; ++w) {
                float4 v = __ldg(rowp + w * C4);
                acc[t].x = fmaxf(acc[t].x, v.x);
                acc[t].y = fmaxf(acc[t].y, v.y);
                acc[t].z = fmaxf(acc[t].z, v.z);
                acc[t].w = fmaxf(acc[t].w, v.w);
            }
        }
    }

    #pragma unroll
    for (int t = 0; t < 7; ++t)
        *(float4*)&sacc[hp][t][lane * 4] = acc[t];
    __syncthreads();

    // combine 4 h-phases for channel c = tid, fix empties, transpose-stage
    {
        int c = tid;
        #pragma unroll
        for (int t = 0; t < 7; ++t) {
            float m = fmaxf(fmaxf(sacc[0][t][c], sacc[1][t][c]),
                            fmaxf(sacc[2][t][c], sacc[3][t][c]));
            tr[c][t] = (m == -CUDART_INF_F) ? 0.0f : m;
        }
    }
    __syncthreads();

    // writeback: out[r][half*128 + c][ph*7 + pw], 128 runs of 7 floats
    float* dst = out + ((size_t)r * C_CH + half * 128) * NBINS + ph * PW;
    for (int j = tid; j < 128 * 7; j += 128) {
        int c2 = j / 7;
        int bl = j - c2 * 7;
        dst[c2 * NBINS + bl] = tr[c2][bl];
    }
}

extern "C" void kernel_launch(void* const* d_in, const int* in_sizes, int n_in,
                              void* d_out, int out_size)
{
    const float* feat = (const float*)d_in[0];
    const float* rois = (const float*)d_in[1];
    float* out = (float*)d_out;

    dim3 tgrid(HW / 32, C_CH / 32, N_IMG);
    dim3 tblock(8, 32);
    transpose_kernel<<<tgrid, tblock>>>(feat, rois);

    pool_kernel<<<R_ROI * 2 * PH, 128>>>(out);
}

// round 14
// speedup vs baseline: 1.2871x; 1.2871x over previous
#include <cuda_runtime.h>
#include <math_constants.h>

// Problem constants (from reference setup_inputs)
#define N_IMG 2
#define C_CH  256
#define H_F   64
#define W_F   64
#define HW    (H_F * W_F)
#define R_ROI 128
#define PH    7
#define PW    7
#define NBINS (PH * PW)   // 49
#define SCALE 0.0625f
#define C4    (C_CH / 4)       // 64 float4 per pixel
#define ROWSTRIDE4 (W_F * C4)  // 4096 float4 per feature row

// NHWC scratch: [b][h][w][c], 8 MB
__device__ float TFEAT[N_IMG * HW * C_CH];
// packed bounds per (r, bin): b<<28 | hs<<21 | he<<14 | ws<<7 | we
__device__ unsigned int BNDS[R_ROI * NBINS];

// ---------------------------------------------------------------------------
// Kernel 1: NCHW -> NHWC transpose (float4 both sides) + bounds precompute
// folded into the first 25 blocks. Bounds arithmetic VERBATIM bit-exact.
// ---------------------------------------------------------------------------
__global__ __launch_bounds__(256) void transpose_kernel(const float* __restrict__ feat,
                                                        const float* __restrict__ rois)
{
    __shared__ float tile[32][33];
    int b   = blockIdx.z;
    int hw0 = blockIdx.x * 32;
    int c0  = blockIdx.y * 32;
    int tx  = threadIdx.x;   // 0..7
    int ty  = threadIdx.y;   // 0..31
    int tid = ty * 8 + tx;

    if (blockIdx.y == 0 && blockIdx.z == 0 && blockIdx.x < 25) {
        int idx = blockIdx.x * 256 + tid;
        if (idx < R_ROI * NBINS) {
            int r   = idx / NBINS;
            int bin = idx - r * NBINS;
            int ph  = bin / PW;
            int pw  = bin - ph * PW;

            const float* roi = rois + r * 5;
            int bb = (int)roi[0];
            int sw = (int)rintf(roi[1] * SCALE);
            int sh_ = (int)rintf(roi[2] * SCALE);
            int ew = (int)rintf(roi[3] * SCALE);
            int eh = (int)rintf(roi[4] * SCALE);

            float roi_w = (float)max(ew - sw + 1, 1);
            float roi_h = (float)max(eh - sh_ + 1, 1);
            float bin_h = roi_h * (1.0f / PH);   // bit-exact vs reference
            float bin_w = roi_w * (1.0f / PW);

            int hs = min(max((int)floorf((float)ph * bin_h) + sh_, 0), H_F);
            int he = min(max((int)ceilf(((float)ph + 1.0f) * bin_h) + sh_, 0), H_F);
            int ws = min(max((int)floorf((float)pw * bin_w) + sw, 0), W_F);
            int we = min(max((int)ceilf(((float)pw + 1.0f) * bin_w) + sw, 0), W_F);

            BNDS[idx] = ((unsigned)bb << 28) | ((unsigned)hs << 21) |
                        ((unsigned)he << 14) | ((unsigned)ws << 7) | (unsigned)we;
        }
    }

    const float4* src4 = (const float4*)(feat + (size_t)b * C_CH * HW);
    float4*       dst4 = (float4*)(TFEAT + (size_t)b * HW * C_CH);

    float4 v = src4[(size_t)(c0 + ty) * (HW / 4) + (hw0 / 4) + tx];
    tile[ty][4 * tx + 0] = v.x;
    tile[ty][4 * tx + 1] = v.y;
    tile[ty][4 * tx + 2] = v.z;
    tile[ty][4 * tx + 3] = v.w;
    __syncthreads();

    float4 o;
    o.x = tile[4 * tx + 0][ty];
    o.y = tile[4 * tx + 1][ty];
    o.z = tile[4 * tx + 2][ty];
    o.w = tile[4 * tx + 3][ty];
    dst4[(size_t)(hw0 + ty) * C4 + (c0 / 4) + tx] = o;
}

// ---------------------------------------------------------------------------
// Kernel 2: pool + fused writeback.
// Warp = (r, qtr, bin), half-warp pixel-pairing (lanes 0-15: col w0+wh=0,
// lanes 16-31: wh=1). Batch = 4h x 4w via 8 INDEPENDENT LDG.128 issued
// back-to-back -> the average 3.2x3.2 bin completes in ONE latency exposure.
// Clamped duplicate reads (max idempotent) keep it remainder-free.
// ---------------------------------------------------------------------------
__global__ __launch_bounds__(224) void pool_kernel(float* __restrict__ out)
{
    __shared__ float sh[PH * 68];    // [bin_local][c_local 0..63]

    int blk  = blockIdx.x;           // r*28 + qtr*7 + g
    int g    = blk % 7;
    int qtr  = (blk / 7) & 3;
    int r    = blk / 28;
    int tid  = threadIdx.x;
    int warp = tid >> 5;             // 0..6 = pw (ph = g)
    int lane = tid & 31;
    int cq   = lane & 15;            // channel quad within the 64-ch quarter
    int wh   = lane >> 4;            // 0/1 pixel-column offset

    unsigned bnd = __ldg(&BNDS[r * NBINS + g * 7 + warp]);
    int we  = bnd & 0x7f;
    int ws  = (bnd >> 7) & 0x7f;
    int he  = (bnd >> 14) & 0x7f;
    int hs  = (bnd >> 21) & 0x7f;
    int b   = bnd >> 28;

    float4 ma;
    if ((he <= hs) || (we <= ws)) {
        ma = make_float4(0.f, 0.f, 0.f, 0.f);
    } else {
        ma = make_float4(-CUDART_INF_F, -CUDART_INF_F, -CUDART_INF_F, -CUDART_INF_F);
        const float4* base = (const float4*)TFEAT + (b * HW * C4 + qtr * 16 + cq);
        int wlast = we - 1;
        int hlast = he - 1;
        for (int h0 = hs; h0 < he; h0 += 4) {
            const float4* r0 = base + h0 * ROWSTRIDE4;
            const float4* r1 = base + min(h0 + 1, hlast) * ROWSTRIDE4;
            const float4* r2 = base + min(h0 + 2, hlast) * ROWSTRIDE4;
            const float4* r3 = base + min(h0 + 3, hlast) * ROWSTRIDE4;
            for (int w0 = ws; w0 < we; w0 += 4) {
                int wa = (min(w0 + wh,     wlast)) * C4;
                int wb = (min(w0 + 2 + wh, wlast)) * C4;
                // 8 independent loads, issued before any consumption
                float4 v0 = __ldg(r0 + wa);
                float4 v1 = __ldg(r0 + wb);
                float4 v2 = __ldg(r1 + wa);
                float4 v3 = __ldg(r1 + wb);
                float4 v4 = __ldg(r2 + wa);
                float4 v5 = __ldg(r2 + wb);
                float4 v6 = __ldg(r3 + wa);
                float4 v7 = __ldg(r3 + wb);
                // tree reduce
                float mx = fmaxf(fmaxf(fmaxf(v0.x, v1.x), fmaxf(v2.x, v3.x)),
                                 fmaxf(fmaxf(v4.x, v5.x), fmaxf(v6.x, v7.x)));
                float my = fmaxf(fmaxf(fmaxf(v0.y, v1.y), fmaxf(v2.y, v3.y)),
                                 fmaxf(fmaxf(v4.y, v5.y), fmaxf(v6.y, v7.y)));
                float mz = fmaxf(fmaxf(fmaxf(v0.z, v1.z), fmaxf(v2.z, v3.z)),
                                 fmaxf(fmaxf(v4.z, v5.z), fmaxf(v6.z, v7.z)));
                float mw = fmaxf(fmaxf(fmaxf(v0.w, v1.w), fmaxf(v2.w, v3.w)),
                                 fmaxf(fmaxf(v4.w, v5.w), fmaxf(v6.w, v7.w)));
                ma.x = fmaxf(ma.x, mx);
                ma.y = fmaxf(ma.y, my);
                ma.z = fmaxf(ma.z, mz);
                ma.w = fmaxf(ma.w, mw);
            }
        }
        // combine the two pixel-column halves
        ma.x = fmaxf(ma.x, __shfl_xor_sync(0xffffffffu, ma.x, 16));
        ma.y = fmaxf(ma.y, __shfl_xor_sync(0xffffffffu, ma.y, 16));
        ma.z = fmaxf(ma.z, __shfl_xor_sync(0xffffffffu, ma.z, 16));
        ma.w = fmaxf(ma.w, __shfl_xor_sync(0xffffffffu, ma.w, 16));
    }

    if (wh == 0)
        *(float4*)&sh[warp * 68 + cq * 4] = ma;
    __syncthreads();

    // writeback: out[r][qtr*64 + c][g*7 + binl], 64 runs of 7 floats.
    float* dst = out + (size_t)r * C_CH * NBINS + (size_t)(qtr * 64) * NBINS + g * 7;
    int c0   = tid / 7;          // 0..31
    int binl = tid - c0 * 7;     // 0..6
    #pragma unroll
    for (int it = 0; it < 2; ++it) {
        int c = c0 + it * 32;
        dst[c * NBINS + binl] = sh[binl * 68 + c];
    }
}

extern "C" void kernel_launch(void* const* d_in, const int* in_sizes, int n_in,
                              void* d_out, int out_size)
{
    const float* feat = (const float*)d_in[0];
    const float* rois = (const float*)d_in[1];
    float* out = (float*)d_out;

    dim3 tgrid(HW / 32, C_CH / 32, N_IMG);
    dim3 tblock(8, 32);
    transpose_kernel<<<tgrid, tblock>>>(feat, rois);

    pool_kernel<<<R_ROI * 4 * 7, 224>>>(out);
}

// round 15
// speedup vs baseline: 1.4411x; 1.1196x over previous
#include <cuda_runtime.h>
#include <math_constants.h>

// Problem constants (from reference setup_inputs)
#define N_IMG 2
#define C_CH  256
#define H_F   64
#define W_F   64
#define HW    (H_F * W_F)
#define R_ROI 128
#define PH    7
#define PW    7
#define NBINS (PH * PW)   // 49
#define SCALE 0.0625f
#define C4    (C_CH / 4)       // 64 float4 per pixel
#define ROWSTRIDE4 (W_F * C4)  // 4096 float4 per feature row

// NHWC scratch: [b][h][w][c], 8 MB
__device__ float TFEAT[N_IMG * HW * C_CH];

// ---------------------------------------------------------------------------
// Kernel 1: NCHW -> NHWC transpose, float4 both sides (round-5 verbatim,
// the fastest measured transpose: ~2.0us).
// ---------------------------------------------------------------------------
__global__ __launch_bounds__(256) void transpose_kernel(const float* __restrict__ feat)
{
    __shared__ float tile[32][33];   // [c_local][hw_local]
    int b   = blockIdx.z;
    int hw0 = blockIdx.x * 32;
    int c0  = blockIdx.y * 32;
    int tx  = threadIdx.x;   // 0..7
    int ty  = threadIdx.y;   // 0..31

    const float4* src4 = (const float4*)(feat + (size_t)b * C_CH * HW);
    float4*       dst4 = (float4*)(TFEAT + (size_t)b * HW * C_CH);

    float4 v = src4[(size_t)(c0 + ty) * (HW / 4) + (hw0 / 4) + tx];
    tile[ty][4 * tx + 0] = v.x;
    tile[ty][4 * tx + 1] = v.y;
    tile[ty][4 * tx + 2] = v.z;
    tile[ty][4 * tx + 3] = v.w;
    __syncthreads();

    float4 o;
    o.x = tile[4 * tx + 0][ty];
    o.y = tile[4 * tx + 1][ty];
    o.z = tile[4 * tx + 2][ty];
    o.w = tile[4 * tx + 3][ty];
    dst4[(size_t)(hw0 + ty) * C4 + (c0 / 4) + tx] = o;
}

// ---------------------------------------------------------------------------
// Kernel 2: pool + fused writeback.
// Round-5 task shape (block = (r, half, bin-group g), 7 warps, warp = one
// bin x 128 channels, lane = float4) + round-12 software pipelining applied
// to the 2x2 batch: the NEXT batch's 4 independent LDG.128 are issued before
// the CURRENT batch is reduced -> 8 loads sustained in flight, exact round-5
// load footprint. Clamped duplicate reads keep it remainder-free (max
// idempotent). Bin-bound arithmetic verbatim from the bit-exact kernel.
// ---------------------------------------------------------------------------
__global__ __launch_bounds__(224) void pool_kernel(const float* __restrict__ rois,
                                                   float* __restrict__ out)
{
    __shared__ float sh[PH * 132];   // [bin_local][c_local]

    int blk  = blockIdx.x;           // r*14 + half*7 + g
    int g    = blk % 7;
    int half = (blk / 7) & 1;
    int r    = blk / 14;
    int tid  = threadIdx.x;
    int warp = tid >> 5;             // 0..6 = bin_local (pw; ph = g)
    int lane = tid & 31;

    const float* roi = rois + r * 5;
    int b  = (int)roi[0];
    int sw = (int)rintf(roi[1] * SCALE);
    int sh_ = (int)rintf(roi[2] * SCALE);
    int ew = (int)rintf(roi[3] * SCALE);
    int eh = (int)rintf(roi[4] * SCALE);

    float roi_w = (float)max(ew - sw + 1, 1);
    float roi_h = (float)max(eh - sh_ + 1, 1);
    float bin_h = roi_h * (1.0f / PH);   // bit-exact vs reference
    float bin_w = roi_w * (1.0f / PW);

    int ph = g;
    int pw = warp;
    int hs = min(max((int)floorf((float)ph * bin_h) + sh_, 0), H_F);
    int he = min(max((int)ceilf(((float)ph + 1.0f) * bin_h) + sh_, 0), H_F);
    int ws = min(max((int)floorf((float)pw * bin_w) + sw, 0), W_F);
    int we = min(max((int)ceilf(((float)pw + 1.0f) * bin_w) + sw, 0), W_F);

    float4 ma;
    if ((he <= hs) || (we <= ws)) {
        ma = make_float4(0.f, 0.f, 0.f, 0.f);
    } else {
        ma = make_float4(-CUDART_INF_F, -CUDART_INF_F, -CUDART_INF_F, -CUDART_INF_F);
        const float4* base = (const float4*)TFEAT + (b * HW * C4 + half * 32 + lane);
        int hlast = he - 1;
        int wlast = we - 1;
        int nh = (he - hs + 1) >> 1;     // 2-row batches
        int nw = (we - ws + 1) >> 1;     // 2-col batches
        int total = nh * nw;

        // ---- load batch 0 ----
        int hi = hs, wi = ws;
        const float4* r0 = base + hi * ROWSTRIDE4;
        const float4* r1 = base + min(hi + 1, hlast) * ROWSTRIDE4;
        int wa = wi * C4;
        int wb = min(wi + 1, wlast) * C4;
        float4 A0 = __ldg(r0 + wa);
        float4 A1 = __ldg(r0 + wb);
        float4 A2 = __ldg(r1 + wa);
        float4 A3 = __ldg(r1 + wb);

        for (int t = 1; t < total; ++t) {
            // advance batch coords (predicated wrap)
            int wn = wi + 2;
            bool wrap = (wn >= we);
            wi = wrap ? ws : wn;
            hi = wrap ? hi + 2 : hi;

            // prefetch next batch BEFORE reducing current (8 loads in flight)
            const float4* q0 = base + hi * ROWSTRIDE4;
            const float4* q1 = base + min(hi + 1, hlast) * ROWSTRIDE4;
            int qa = wi * C4;
            int qb = min(wi + 1, wlast) * C4;
            float4 B0 = __ldg(q0 + qa);
            float4 B1 = __ldg(q0 + qb);
            float4 B2 = __ldg(q1 + qa);
            float4 B3 = __ldg(q1 + qb);

            // reduce current batch
            ma.x = fmaxf(ma.x, fmaxf(fmaxf(A0.x, A1.x), fmaxf(A2.x, A3.x)));
            ma.y = fmaxf(ma.y, fmaxf(fmaxf(A0.y, A1.y), fmaxf(A2.y, A3.y)));
            ma.z = fmaxf(ma.z, fmaxf(fmaxf(A0.z, A1.z), fmaxf(A2.z, A3.z)));
            ma.w = fmaxf(ma.w, fmaxf(fmaxf(A0.w, A1.w), fmaxf(A2.w, A3.w)));

            A0 = B0; A1 = B1; A2 = B2; A3 = B3;
        }
        // reduce last batch
        ma.x = fmaxf(ma.x, fmaxf(fmaxf(A0.x, A1.x), fmaxf(A2.x, A3.x)));
        ma.y = fmaxf(ma.y, fmaxf(fmaxf(A0.y, A1.y), fmaxf(A2.y, A3.y)));
        ma.z = fmaxf(ma.z, fmaxf(fmaxf(A0.z, A1.z), fmaxf(A2.z, A3.z)));
        ma.w = fmaxf(ma.w, fmaxf(fmaxf(A0.w, A1.w), fmaxf(A2.w, A3.w)));
    }

    *(float4*)&sh[warp * 132 + lane * 4] = ma;
    __syncthreads();

    // writeback: out[r][half*128 + c][g*7 + binl], 128 runs of 7 floats.
    // stride 224 = 32*7 -> binl invariant, c += 32 per iteration.
    float* dst = out + (size_t)r * C_CH * NBINS + (size_t)half * 128 * NBINS + g * 7;
    int c0   = tid / 7;          // 0..31
    int binl = tid - c0 * 7;     // 0..6
    #pragma unroll
    for (int it = 0; it < 4; ++it) {
        int c = c0 + it * 32;
        dst[c * NBINS + binl] = sh[binl * 132 + c];
    }
}

extern "C" void kernel_launch(void* const* d_in, const int* in_sizes, int n_in,
                              void* d_out, int out_size)
{
    const float* feat = (const float*)d_in[0];
    const float* rois = (const float*)d_in[1];
    float* out = (float*)d_out;

    dim3 tgrid(HW / 32, C_CH / 32, N_IMG);
    dim3 tblock(8, 32);
    transpose_kernel<<<tgrid, tblock>>>(feat);

    pool_kernel<<<R_ROI * 2 * 7, 224>>>(rois, out);
}